// round 2
// baseline (speedup 1.0000x reference)
#include <cuda_runtime.h>
#include <cstddef>

#define B_DIM 4096
#define K_DIM 64
#define D_DIM 512
#define N_AGENTS 64
#define NEG_INF -1e9f
#define THREADS 512
#define STAGE_K 32            // rows of h staged in smem (64 KB); rest re-read via L2

__global__ __launch_bounds__(THREADS, 3)
void block_diag_agg_kernel(const float* __restrict__ h,
                           const float* __restrict__ keys,
                           const int* __restrict__ sigma,
                           float* __restrict__ out) {
    extern __shared__ float sh[];            // STAGE_K * 512 floats = 64 KB
    __shared__ float s_logits[K_DIM];
    __shared__ float s_alpha[K_DIM];

    const int b    = blockIdx.x;
    const int tid  = threadIdx.x;
    const int warp = tid >> 5;
    const int lane = tid & 31;

    const float* hb = h + (size_t)b * (K_DIM * D_DIM);
    const int*   sb = sigma + (size_t)b * K_DIM;

    // ---- Phase 1: per-slot dot products; stage first STAGE_K rows into smem ----
    // 16 warps, each handles 4 consecutive k slots (warp-uniform k).
    #pragma unroll
    for (int i = 0; i < 4; i++) {
        const int k = warp * 4 + i;
        const int sid    = sb[k];
        const bool valid = (sid < N_AGENTS);
        const float4* hrow = (const float4*)(hb + (size_t)k * D_DIM);
        const float4* krow = (const float4*)(keys + (size_t)(valid ? sid : 0) * D_DIM);

        float acc = 0.0f;
        #pragma unroll
        for (int j = 0; j < 4; j++) {
            const int idx = lane + 32 * j;           // 0..127 float4 per row
            float4 hv = hrow[idx];
            float4 kv = krow[idx];
            acc = fmaf(hv.x, kv.x, acc);
            acc = fmaf(hv.y, kv.y, acc);
            acc = fmaf(hv.z, kv.z, acc);
            acc = fmaf(hv.w, kv.w, acc);
            if (k < STAGE_K)                          // warp-uniform predicate
                ((float4*)sh)[k * (D_DIM / 4) + idx] = hv;
        }
        #pragma unroll
        for (int off = 16; off > 0; off >>= 1)
            acc += __shfl_xor_sync(0xFFFFFFFFu, acc, off);
        if (lane == 0)
            s_logits[k] = valid ? acc : NEG_INF;
    }
    __syncthreads();

    // ---- Phase 2: softmax over K=64 (warp 0 only, 2 logits per lane) ----
    if (warp == 0) {
        float l0 = s_logits[lane];
        float l1 = s_logits[lane + 32];
        float m = fmaxf(l0, l1);
        #pragma unroll
        for (int off = 16; off > 0; off >>= 1)
            m = fmaxf(m, __shfl_xor_sync(0xFFFFFFFFu, m, off));
        float e0 = expf(l0 - m);
        float e1 = expf(l1 - m);
        float s = e0 + e1;
        #pragma unroll
        for (int off = 16; off > 0; off >>= 1)
            s += __shfl_xor_sync(0xFFFFFFFFu, s, off);
        float inv = 1.0f / s;
        s_alpha[lane]      = e0 * inv;
        s_alpha[lane + 32] = e1 * inv;
    }
    __syncthreads();

    // ---- Phase 3: weighted pooling; thread tid owns dim d = tid ----
    float acc_s = 0.0f;
    #pragma unroll 8
    for (int k = 0; k < STAGE_K; k++)               // staged half from smem
        acc_s = fmaf(s_alpha[k], sh[k * D_DIM + tid], acc_s);

    float acc_g = 0.0f;
    const float* hg = hb + (size_t)STAGE_K * D_DIM + tid;
    #pragma unroll 8
    for (int k = 0; k < K_DIM - STAGE_K; k++)       // global half (L2-hit re-read)
        acc_g = fmaf(s_alpha[STAGE_K + k], hg[(size_t)k * D_DIM], acc_g);

    out[(size_t)b * D_DIM + tid] = acc_s + acc_g;
}

extern "C" void kernel_launch(void* const* d_in, const int* in_sizes, int n_in,
                              void* d_out, int out_size) {
    const float* h     = (const float*)d_in[0];
    const float* keys  = (const float*)d_in[1];
    const int*   sigma = (const int*)d_in[2];
    float*       out   = (float*)d_out;

    const int smem_bytes = STAGE_K * D_DIM * (int)sizeof(float);  // 64 KB
    cudaFuncSetAttribute(block_diag_agg_kernel,
                         cudaFuncAttributeMaxDynamicSharedMemorySize, smem_bytes);

    block_diag_agg_kernel<<<B_DIM, THREADS, smem_bytes>>>(h, keys, sigma, out);
}

// round 3
// speedup vs baseline: 1.2989x; 1.2989x over previous
#include <cuda_runtime.h>
#include <cstddef>

#define B_DIM 4096
#define K_DIM 64
#define D_DIM 512
#define N_AGENTS 64
#define NEG_INF -1e9f
#define THREADS 512

__global__ __launch_bounds__(THREADS, 3)
void block_diag_agg_kernel(const float* __restrict__ h,
                           const float* __restrict__ keys,
                           const int* __restrict__ sigma,
                           float* __restrict__ out) {
    __shared__ float s_logits[K_DIM];
    __shared__ float s_alpha[K_DIM];

    const int b    = blockIdx.x;
    const int tid  = threadIdx.x;
    const int warp = tid >> 5;
    const int lane = tid & 31;

    const float* hb = h + (size_t)b * (K_DIM * D_DIM);
    const int*   sb = sigma + (size_t)b * K_DIM;

    // ---- Phase 1: per-slot dot products (no staging). 16 warps x 4 k-slots. ----
    #pragma unroll
    for (int i = 0; i < 4; i++) {
        const int k = warp * 4 + i;
        const int sid    = sb[k];
        const bool valid = (sid < N_AGENTS);
        const float4* hrow = (const float4*)(hb + (size_t)k * D_DIM);
        const float4* krow = (const float4*)(keys + (size_t)(valid ? sid : 0) * D_DIM);

        float acc = 0.0f;
        #pragma unroll
        for (int j = 0; j < 4; j++) {
            const int idx = lane + 32 * j;            // 0..127 float4 per row
            float4 hv = __ldcg(&hrow[idx]);           // stream through L2, don't pollute L1
            float4 kv = __ldg(&krow[idx]);            // keys stay L1-resident
            acc = fmaf(hv.x, kv.x, acc);
            acc = fmaf(hv.y, kv.y, acc);
            acc = fmaf(hv.z, kv.z, acc);
            acc = fmaf(hv.w, kv.w, acc);
        }
        #pragma unroll
        for (int off = 16; off > 0; off >>= 1)
            acc += __shfl_xor_sync(0xFFFFFFFFu, acc, off);
        if (lane == 0)
            s_logits[k] = valid ? acc : NEG_INF;
    }
    __syncthreads();

    // ---- Phase 2: softmax over K=64 (warp 0 only) ----
    if (warp == 0) {
        float l0 = s_logits[lane];
        float l1 = s_logits[lane + 32];
        float m = fmaxf(l0, l1);
        #pragma unroll
        for (int off = 16; off > 0; off >>= 1)
            m = fmaxf(m, __shfl_xor_sync(0xFFFFFFFFu, m, off));
        float e0 = __expf(l0 - m);
        float e1 = __expf(l1 - m);
        float s = e0 + e1;
        #pragma unroll
        for (int off = 16; off > 0; off >>= 1)
            s += __shfl_xor_sync(0xFFFFFFFFu, s, off);
        float inv = 1.0f / s;
        s_alpha[lane]      = e0 * inv;
        s_alpha[lane + 32] = e1 * inv;
    }
    __syncthreads();

    // ---- Phase 3: weighted pooling; thread tid owns dim d = tid.
    //      Re-read h[b] from L2 (resident: read moments ago by this CTA). ----
    const float* hg = hb + tid;
    float acc0 = 0.0f, acc1 = 0.0f, acc2 = 0.0f, acc3 = 0.0f;
    #pragma unroll
    for (int k = 0; k < K_DIM; k += 4) {
        acc0 = fmaf(s_alpha[k + 0], __ldcg(&hg[(size_t)(k + 0) * D_DIM]), acc0);
        acc1 = fmaf(s_alpha[k + 1], __ldcg(&hg[(size_t)(k + 1) * D_DIM]), acc1);
        acc2 = fmaf(s_alpha[k + 2], __ldcg(&hg[(size_t)(k + 2) * D_DIM]), acc2);
        acc3 = fmaf(s_alpha[k + 3], __ldcg(&hg[(size_t)(k + 3) * D_DIM]), acc3);
    }
    out[(size_t)b * D_DIM + tid] = (acc0 + acc1) + (acc2 + acc3);
}

extern "C" void kernel_launch(void* const* d_in, const int* in_sizes, int n_in,
                              void* d_out, int out_size) {
    const float* h     = (const float*)d_in[0];
    const float* keys  = (const float*)d_in[1];
    const int*   sigma = (const int*)d_in[2];
    float*       out   = (float*)d_out;

    block_diag_agg_kernel<<<B_DIM, THREADS>>>(h, keys, sigma, out);
}